// round 8
// baseline (speedup 1.0000x reference)
#include <cuda_runtime.h>

#define NL  2048
#define NE  256
#define NH  8
#define NHW 32
#define NB  2
#define KS  4              // k-split factor
#define KT  16             // key tile

// Scratch (static device globals -- no runtime allocation)
__device__ float g_Q [NB*NH*NL*NHW];      // [bh][l][d] (pre-scaled)
__device__ float g_Kt[NB*NH*NHW*NL];      // [bh][d][l]
__device__ float g_V [NB*NH*NL*NHW];      // [bh][l][d]
__device__ float g_Y [NB*NL*NE];
__device__ float g_Opart[KS*NB*NL*NE];    // partial numerators
__device__ float g_Lpart[KS*NB*NL*NH];    // partial denominators

typedef unsigned long long u64;

static __device__ __forceinline__ u64 pack2(float lo, float hi) {
    u64 r; asm("mov.b64 %0, {%1,%2};" : "=l"(r) : "f"(lo), "f"(hi)); return r;
}
static __device__ __forceinline__ void unpack2(u64 a, float& lo, float& hi) {
    asm("mov.b64 {%0,%1}, %2;" : "=f"(lo), "=f"(hi) : "l"(a));
}
static __device__ __forceinline__ void fma2(u64& acc, u64 a, u64 b) {
    asm("fma.rn.f32x2 %0, %1, %2, %3;" : "=l"(acc) : "l"(a), "l"(b), "l"(acc));
}
static __device__ __forceinline__ void cp16(void* dst, const void* src) {
    unsigned d = (unsigned)__cvta_generic_to_shared(dst);
    asm volatile("cp.async.cg.shared.global [%0], [%1], 16;" :: "r"(d), "l"(src));
}
static __device__ __forceinline__ void cp_commit() {
    asm volatile("cp.async.commit_group;");
}
static __device__ __forceinline__ void cp_wait1() {
    asm volatile("cp.async.wait_group 1;");
}

// ---------------------------------------------------------------------------
// GEMM (NT): C[m][n] = sum_k A[m][k]*W[n][k], K=256. 128x64 tile, 256 thr,
// 8m x 4n micro-tile (m-paired f32x2). Register-prefetch pipeline: gmem
// loads for chunk c+1 issued before the compute loop of chunk c.
// EPI 0: scatter Q/Kt/V.  EPI 1: out + bias.
// ---------------------------------------------------------------------------
template<int EPI>
__global__ __launch_bounds__(256) void gemm_nt(const float* __restrict__ A,
                                               const float* __restrict__ W,
                                               const float* __restrict__ bo,
                                               float* __restrict__ out)
{
    __shared__ __align__(16) float As[32][132];
    __shared__ __align__(16) float Bs[32][68];
    const int tid = threadIdx.x;
    const int tx = tid & 15, ty = tid >> 4;
    const int m0 = blockIdx.x * 128, n0 = blockIdx.y * 64;

    const int rowA = tid >> 1,               // 0..127 (2 lanes per row)
              cA   = (tid & 1) << 4;         // 0 or 16
    const int rowB = tid >> 2,               // 0..63  (4 lanes per row)
              cB   = (tid & 3) << 3;         // 0,8,16,24

    u64 acc[4][4];
    #pragma unroll
    for (int p = 0; p < 4; p++)
        #pragma unroll
        for (int j = 0; j < 4; j++) acc[p][j] = 0ULL;

    float4 xa[4], wa[2];
    auto ldg = [&](int kc) {
        #pragma unroll
        for (int r = 0; r < 4; r++)
            xa[r] = *(const float4*)&A[(size_t)(m0 + rowA) * 256 + kc + cA + r * 4];
        #pragma unroll
        for (int r = 0; r < 2; r++)
            wa[r] = *(const float4*)&W[(size_t)(n0 + rowB) * 256 + kc + cB + r * 4];
    };
    ldg(0);

    for (int kc = 0; kc < 256; kc += 32) {
        // scatter register stage into smem (transposed)
        #pragma unroll
        for (int r = 0; r < 4; r++) {
            int c = cA + r * 4;
            As[c+0][rowA] = xa[r].x; As[c+1][rowA] = xa[r].y;
            As[c+2][rowA] = xa[r].z; As[c+3][rowA] = xa[r].w;
        }
        #pragma unroll
        for (int r = 0; r < 2; r++) {
            int c = cB + r * 4;
            Bs[c+0][rowB] = wa[r].x; Bs[c+1][rowB] = wa[r].y;
            Bs[c+2][rowB] = wa[r].z; Bs[c+3][rowB] = wa[r].w;
        }
        __syncthreads();
        if (kc < 224) ldg(kc + 32);          // prefetch next chunk into regs

        #pragma unroll
        for (int k = 0; k < 32; k++) {
            ulonglong2 aA = *(const ulonglong2*)&As[k][ty * 8];
            ulonglong2 aB = *(const ulonglong2*)&As[k][ty * 8 + 4];
            float4 b4 = *(const float4*)&Bs[k][tx * 4];
            u64 bb;
            bb = pack2(b4.x, b4.x);
            fma2(acc[0][0], aA.x, bb); fma2(acc[1][0], aA.y, bb);
            fma2(acc[2][0], aB.x, bb); fma2(acc[3][0], aB.y, bb);
            bb = pack2(b4.y, b4.y);
            fma2(acc[0][1], aA.x, bb); fma2(acc[1][1], aA.y, bb);
            fma2(acc[2][1], aB.x, bb); fma2(acc[3][1], aB.y, bb);
            bb = pack2(b4.z, b4.z);
            fma2(acc[0][2], aA.x, bb); fma2(acc[1][2], aA.y, bb);
            fma2(acc[2][2], aB.x, bb); fma2(acc[3][2], aB.y, bb);
            bb = pack2(b4.w, b4.w);
            fma2(acc[0][3], aA.x, bb); fma2(acc[1][3], aA.y, bb);
            fma2(acc[2][3], aB.x, bb); fma2(acc[3][3], aB.y, bb);
        }
        __syncthreads();
    }

    #pragma unroll
    for (int p = 0; p < 4; p++) {
        int m = m0 + ty * 8 + 2 * p;
        #pragma unroll
        for (int j = 0; j < 4; j++) {
            float v0, v1; unpack2(acc[p][j], v0, v1);
            int n = n0 + tx * 4 + j;
            if (EPI == 0) {
                int hh = n / 96, rem = n % 96;
                int part = rem >> 5, c = rem & 31;
                int bb_ = m >> 11, l = m & 2047;
                int bh = bb_ * NH + hh;
                if (part == 1) {
                    float* d = g_Kt + (size_t)bh * (NHW * NL) + (size_t)c * NL + l;
                    d[0] = v0; d[1] = v1;
                } else {
                    float* d = (part == 0 ? g_Q : g_V)
                             + ((size_t)bh * NL + l) * NHW + c;
                    float sc = (part == 0) ? 0.17677669529663687f : 1.0f;
                    d[0]   = v0 * sc;
                    d[NHW] = v1 * sc;
                }
            } else {
                float bias_ = bo[n];
                out[(size_t)m * NE + n]       = v0 + bias_;
                out[(size_t)(m + 1) * NE + n] = v1 + bias_;
            }
        }
    }
}

// ---------------------------------------------------------------------------
// Attention v4: lane=query, warp=head, CTA = 32q x 8h over a 512-key split.
// k-tile 16, smem 96KB -> 2 CTAs/SM. exp fused into AV per key-pair so p[]
// never lives as an array -> peak regs ~105 (< 128 cap) -> no spills.
// ---------------------------------------------------------------------------
// smem float offsets
#define SM_K   0            // [h][s][d32][k16]    8*2*32*16
#define SM_V2  8192         // [h][s][k16][d32]    8*2*16*32
#define SM_B   16384        // [s][q32][32 units of 4w, XOR-swizzled] 2*4096
#define SMEMF  24576
#define SMEMB  (SMEMF*4)

__global__ __launch_bounds__(256, 2) void attn4(const float* __restrict__ bias)
{
    extern __shared__ float sm[];
    const int tid = threadIdx.x, lane = tid & 31, h = tid >> 5;
    const int q0 = blockIdx.x * 32;
    const int b  = blockIdx.y >> 2;
    const int ks = blockIdx.y & 3;
    const int bh = b * NH + h;
    const int kbase0 = ks * (NL / KS);

    const float* Ktb = g_Kt + (size_t)bh * (NHW * NL);
    const float* Vb  = g_V  + (size_t)bh * (NL * NHW);

    float qreg[32];
    {
        const float4* qp = (const float4*)(g_Q + ((size_t)bh * NL + q0 + lane) * NHW);
        #pragma unroll
        for (int i = 0; i < 8; i++) *(float4*)&qreg[i * 4] = qp[i];
    }

    u64 o2[16];
    #pragma unroll
    for (int i = 0; i < 16; i++) o2[i] = 0ULL;
    float lsum0 = 0.f, lsum1 = 0.f;

    float* kW = sm + SM_K  + h * 1024;
    float* vW = sm + SM_V2 + h * 1024;
    const size_t brow = ((size_t)(b * NL + q0)) * (NL * NH);

    auto stage = [&](int s, int kb) {
        // K^T tile for this head: 32d x 16k
        #pragma unroll
        for (int i = 0; i < 4; i++) {
            int m = i * 32 + lane, d = m >> 2, j = m & 3;
            cp16(kW + s * 512 + d * 16 + j * 4,
                 Ktb + (size_t)d * NL + kb + j * 4);
        }
        // V tile: 16k x 32d (contiguous)
        #pragma unroll
        for (int i = 0; i < 4; i++) {
            int m = i * 32 + lane, k = m >> 3, j = m & 7;
            cp16(vW + s * 512 + k * 32 + j * 4,
                 Vb + (size_t)(kb + k) * NHW + j * 4);
        }
        // bias tile: 32q x 16k x 8h, unit u = k*2 + hgrp, swizzled u^(q&31)
        #pragma unroll
        for (int i = 0; i < 4; i++) {
            int m = i * 256 + tid, q = m >> 5, u = m & 31;
            cp16(sm + SM_B + s * 4096 + q * 128 + ((u ^ (q & 31)) << 2),
                 bias + brow + (size_t)q * (NL * NH)
                      + (size_t)(kb + (u >> 1)) * NH + (u & 1) * 4);
        }
    };

    stage(0, kbase0);
    cp_commit();

    const int qm = lane & 31;
    const int hg = h >> 2, h3 = h & 3;

    for (int t = 0; t < (NL / KS) / KT; t++) {
        int s = t & 1;
        if (t < (NL / KS) / KT - 1) stage(s ^ 1, kbase0 + (t + 1) * KT);
        cp_commit();
        cp_wait1();
        __syncthreads();

        // phase 1: scores for all 16 keys (s2[j] = keys 2j, 2j+1)
        u64 s2[8];
        #pragma unroll
        for (int i = 0; i < 8; i++) s2[i] = 0ULL;
        const float* kp = kW + s * 512;
        #pragma unroll
        for (int d = 0; d < 32; d++) {
            u64 qq = pack2(qreg[d], qreg[d]);
            const ulonglong2* kr = (const ulonglong2*)(kp + d * 16);
            #pragma unroll
            for (int i = 0; i < 4; i++) {
                ulonglong2 kk = kr[i];
                fma2(s2[2 * i],     kk.x, qq);
                fma2(s2[2 * i + 1], kk.y, qq);
            }
        }

        // phase 2 (fused): per key-pair, exp(score+bias) then immediate AV
        const float* bbase = sm + SM_B + s * 4096 + lane * 128;
        const float* vp = vW + s * 512;
        #pragma unroll
        for (int j = 0; j < 8; j++) {
            float sa, sb; unpack2(s2[j], sa, sb);
            int k0i = 2 * j, k1i = 2 * j + 1;
            float b0 = bbase[(((k0i * 2 + hg) ^ qm) << 2) + h3];
            float b1 = bbase[(((k1i * 2 + hg) ^ qm) << 2) + h3];
            float p0 = __expf(sa + b0);
            float p1 = __expf(sb + b1);
            lsum0 += p0; lsum1 += p1;
            u64 pp0 = pack2(p0, p0);
            u64 pp1 = pack2(p1, p1);
            const ulonglong2* vr0 = (const ulonglong2*)(vp + k0i * 32);
            const ulonglong2* vr1 = (const ulonglong2*)(vp + k1i * 32);
            #pragma unroll
            for (int i = 0; i < 8; i++) {
                ulonglong2 va = vr0[i];
                fma2(o2[2 * i],     va.x, pp0);
                fma2(o2[2 * i + 1], va.y, pp0);
            }
            #pragma unroll
            for (int i = 0; i < 8; i++) {
                ulonglong2 vb2 = vr1[i];
                fma2(o2[2 * i],     vb2.x, pp1);
                fma2(o2[2 * i + 1], vb2.y, pp1);
            }
        }
        __syncthreads();
    }

    // write partials
    float* op = g_Opart + (((size_t)(ks * NB + b) * NL + q0 + lane)) * NE + h * NHW;
    #pragma unroll
    for (int i = 0; i < 8; i++) {
        float a0, a1, a2, a3;
        unpack2(o2[2 * i],     a0, a1);
        unpack2(o2[2 * i + 1], a2, a3);
        ((float4*)op)[i] = make_float4(a0, a1, a2, a3);
    }
    g_Lpart[((size_t)(ks * NB + b) * NL + q0 + lane) * NH + h] = lsum0 + lsum1;
}

// ---------------------------------------------------------------------------
// combine k-split partials: y = (sum_s o_s) / (sum_s l_s)
// ---------------------------------------------------------------------------
__global__ __launch_bounds__(256) void reduce_k()
{
    int idx = blockIdx.x * 256 + threadIdx.x;       // over NB*NL*NE
    int e = idx & 255;
    int bl = idx >> 8;                               // b*NL + l
    int hh = e >> 5;
    float o = 0.f, l = 0.f;
    #pragma unroll
    for (int s = 0; s < KS; s++) {
        o += g_Opart[((size_t)s * NB * NL + bl) * NE + e];
        l += g_Lpart[((size_t)s * NB * NL + bl) * NH + hh];
    }
    g_Y[(size_t)bl * NE + e] = o / l;
}

// ---------------------------------------------------------------------------
extern "C" void kernel_launch(void* const* d_in, const int* in_sizes, int n_in,
                              void* d_out, int out_size)
{
    const float* x    = (const float*)d_in[0];
    const float* bias = (const float*)d_in[1];
    const float* Wp   = (const float*)d_in[2];
    const float* Wo   = (const float*)d_in[3];
    const float* bo   = (const float*)d_in[4];
    float* out = (float*)d_out;

    float* yptr;
    cudaGetSymbolAddress((void**)&yptr, g_Y);

    cudaFuncSetAttribute(attn4, cudaFuncAttributeMaxDynamicSharedMemorySize,
                         SMEMB);

    gemm_nt<0><<<dim3(32, 12), 256>>>(x, Wp, nullptr, nullptr);
    attn4<<<dim3(NL / 32, NB * KS), 256, SMEMB>>>(bias);
    reduce_k<<<(NB * NL * NE) / 256, 256>>>();
    gemm_nt<1><<<dim3(32, 4), 256>>>(yptr, Wo, bo, out);
}

// round 11
// speedup vs baseline: 1.6258x; 1.6258x over previous
#include <cuda_runtime.h>
#include <cuda_fp16.h>
#include <cstdint>

#define NL  2048
#define NE  256
#define NH  8
#define NHW 32
#define NB  2

// Scratch (static device globals -- no runtime allocation)
__device__ float g_Q  [NB*NH*NL*NHW];     // [bh][l][d] fp32 (pre-scaled)
__device__ float g_K  [NB*NH*NL*NHW];     // [bh][l][d] tf32-hi
__device__ float g_Klo[NB*NH*NL*NHW];     // [bh][l][d] tf32-lo
__device__ float g_V  [NB*NH*NL*NHW];     // tf32-hi
__device__ float g_Vlo[NB*NH*NL*NHW];     // tf32-lo
__device__ float g_Y  [NB*NL*NE];
__device__ float g_Btf[(size_t)NB*NH*NL*NL];   // bias^T [b][h][q][k] fp32

typedef unsigned long long u64;

static __device__ __forceinline__ u64 pack2(float lo, float hi) {
    u64 r; asm("mov.b64 %0, {%1,%2};" : "=l"(r) : "f"(lo), "f"(hi)); return r;
}
static __device__ __forceinline__ void unpack2(u64 a, float& lo, float& hi) {
    asm("mov.b64 {%0,%1}, %2;" : "=f"(lo), "=f"(hi) : "l"(a));
}
static __device__ __forceinline__ void fma2(u64& acc, u64 a, u64 b) {
    asm("fma.rn.f32x2 %0, %1, %2, %3;" : "=l"(acc) : "l"(a), "l"(b), "l"(acc));
}
static __device__ __forceinline__ void cp16(void* dst, const void* src) {
    unsigned d = (unsigned)__cvta_generic_to_shared(dst);
    asm volatile("cp.async.cg.shared.global [%0], [%1], 16;" :: "r"(d), "l"(src));
}
static __device__ __forceinline__ void cp_commit() {
    asm volatile("cp.async.commit_group;");
}
static __device__ __forceinline__ void cp_wait1() {
    asm volatile("cp.async.wait_group 1;");
}
static __device__ __forceinline__ void cp_wait0() {
    asm volatile("cp.async.wait_group 0;");
}
static __device__ __forceinline__ uint32_t tf32_rna_u(float x) {
    uint32_t r; asm("cvt.rna.tf32.f32 %0, %1;" : "=r"(r) : "f"(x)); return r;
}
static __device__ __forceinline__ float tf32_rna_f(float x) {
    return __uint_as_float(tf32_rna_u(x));
}
// tf32 mma m16n8k8, fp32 accumulate (arch-portable tensor path)
static __device__ __forceinline__ void mma_tf32(float* c, const uint32_t* a,
                                                uint32_t b0, uint32_t b1) {
    asm volatile(
        "mma.sync.aligned.m16n8k8.row.col.f32.tf32.tf32.f32 "
        "{%0,%1,%2,%3}, {%4,%5,%6,%7}, {%8,%9}, {%0,%1,%2,%3};"
        : "+f"(c[0]), "+f"(c[1]), "+f"(c[2]), "+f"(c[3])
        : "r"(a[0]), "r"(a[1]), "r"(a[2]), "r"(a[3]), "r"(b0), "r"(b1));
}

// ---------------------------------------------------------------------------
// GEMM (NT): C[m][n] = sum_k A[m][k]*W[n][k], K=256. 128x64 tile, 256 thr.
// EPI 0: scatter Q fp32 (scaled), K/V split into tf32 hi/lo.  EPI 1: +bias.
// ---------------------------------------------------------------------------
template<int EPI>
__global__ __launch_bounds__(256) void gemm_nt(const float* __restrict__ A,
                                               const float* __restrict__ W,
                                               const float* __restrict__ bo,
                                               float* __restrict__ out)
{
    __shared__ __align__(16) float As[32][132];
    __shared__ __align__(16) float Bs[32][68];
    const int tid = threadIdx.x;
    const int tx = tid & 15, ty = tid >> 4;
    const int m0 = blockIdx.x * 128, n0 = blockIdx.y * 64;

    u64 acc[4][4];
    #pragma unroll
    for (int p = 0; p < 4; p++)
        #pragma unroll
        for (int j = 0; j < 4; j++) acc[p][j] = 0ULL;

    for (int kc = 0; kc < 256; kc += 32) {
        #pragma unroll
        for (int r = 0; r < 4; r++) {
            int idx = tid + r * 256;
            int row = idx >> 3, c4 = (idx & 7) << 2;
            float4 xa = *(const float4*)&A[(size_t)(m0 + row) * 256 + kc + c4];
            As[c4+0][row] = xa.x; As[c4+1][row] = xa.y;
            As[c4+2][row] = xa.z; As[c4+3][row] = xa.w;
        }
        #pragma unroll
        for (int r = 0; r < 2; r++) {
            int idx = tid + r * 256;
            int row = idx >> 3, c4 = (idx & 7) << 2;
            float4 wa = *(const float4*)&W[(size_t)(n0 + row) * 256 + kc + c4];
            Bs[c4+0][row] = wa.x; Bs[c4+1][row] = wa.y;
            Bs[c4+2][row] = wa.z; Bs[c4+3][row] = wa.w;
        }
        __syncthreads();
        #pragma unroll
        for (int k = 0; k < 32; k++) {
            ulonglong2 aA = *(const ulonglong2*)&As[k][ty * 8];
            ulonglong2 aB = *(const ulonglong2*)&As[k][ty * 8 + 4];
            float4 b4 = *(const float4*)&Bs[k][tx * 4];
            u64 bb;
            bb = pack2(b4.x, b4.x);
            fma2(acc[0][0], aA.x, bb); fma2(acc[1][0], aA.y, bb);
            fma2(acc[2][0], aB.x, bb); fma2(acc[3][0], aB.y, bb);
            bb = pack2(b4.y, b4.y);
            fma2(acc[0][1], aA.x, bb); fma2(acc[1][1], aA.y, bb);
            fma2(acc[2][1], aB.x, bb); fma2(acc[3][1], aB.y, bb);
            bb = pack2(b4.z, b4.z);
            fma2(acc[0][2], aA.x, bb); fma2(acc[1][2], aA.y, bb);
            fma2(acc[2][2], aB.x, bb); fma2(acc[3][2], aB.y, bb);
            bb = pack2(b4.w, b4.w);
            fma2(acc[0][3], aA.x, bb); fma2(acc[1][3], aA.y, bb);
            fma2(acc[2][3], aB.x, bb); fma2(acc[3][3], aB.y, bb);
        }
        __syncthreads();
    }

    #pragma unroll
    for (int p = 0; p < 4; p++) {
        int m = m0 + ty * 8 + 2 * p;
        #pragma unroll
        for (int j = 0; j < 4; j++) {
            float v0, v1; unpack2(acc[p][j], v0, v1);
            int n = n0 + tx * 4 + j;
            if (EPI == 0) {
                int hh = n / 96, rem = n % 96;
                int part = rem >> 5, c = rem & 31;
                int bb_ = m >> 11, l = m & 2047;
                int bh = bb_ * NH + hh;
                size_t base = ((size_t)bh * NL + l) * NHW + c;
                if (part == 0) {
                    g_Q[base]       = v0 * 0.17677669529663687f;
                    g_Q[base + NHW] = v1 * 0.17677669529663687f;
                } else {
                    float* dh = (part == 1) ? g_K   : g_V;
                    float* dl = (part == 1) ? g_Klo : g_Vlo;
                    float h0 = tf32_rna_f(v0), h1 = tf32_rna_f(v1);
                    dh[base]       = h0;
                    dh[base + NHW] = h1;
                    dl[base]       = tf32_rna_f(v0 - h0);
                    dl[base + NHW] = tf32_rna_f(v1 - h1);
                }
            } else {
                float bias_ = bo[n];
                out[(size_t)m * NE + n]       = v0 + bias_;
                out[(size_t)(m + 1) * NE + n] = v1 + bias_;
            }
        }
    }
}

// ---------------------------------------------------------------------------
// bias transpose: [b][q][k][h] fp32 -> [b][h][q][k] fp32 (HBM-bound)
// ---------------------------------------------------------------------------
__global__ __launch_bounds__(256) void bias_t(const float* __restrict__ bias)
{
    size_t idx = (size_t)blockIdx.x * 256 + threadIdx.x;   // over NB*NL*(NL/2)
    int k2 = idx & 1023;
    size_t rest = idx >> 10;
    int q = rest & 2047;
    int b = (int)(rest >> 11);
    const float4* src = (const float4*)(bias + (((size_t)(b * NL + q)) * NL + 2 * k2) * NH);
    float4 a0 = src[0], a1 = src[1], a2 = src[2], a3 = src[3];
    float f[16];
    *(float4*)&f[0]  = a0; *(float4*)&f[4]  = a1;
    *(float4*)&f[8]  = a2; *(float4*)&f[12] = a3;
    #pragma unroll
    for (int h = 0; h < NH; h++)
        *(float2*)&g_Btf[((size_t)(b * NH + h) * NL + q) * NL + 2 * k2] =
            make_float2(f[h], f[8 + h]);
}

// ---------------------------------------------------------------------------
// Split-precision tf32 mma.sync attention. CTA = (b,h,128q), 8 warps x 16q,
// key tiles of 64, double-buffered cp.async (K/V hi+lo, bias fp32).
//   S = q_hi k_hi + q_lo k_hi + q_hi k_lo   (3-MMA, near-fp32)
//   P = rna(exp(S + bias)); lsum from same rounded P (consistent weights)
//   O += P (V_hi + V_lo)                    (2-MMA)
// ---------------------------------------------------------------------------
#define Q_OFF   0
#define KH_OFF  18432
#define KL_OFF  36864
#define VH_OFF  55296
#define VL_OFF  73728
#define B_OFF   92160
#define P_OFF   161792
#define SM_TOT  196608
// pitches: Q/K/V rows 36 floats (144B); bias rows 68 floats (272B); P rows 68

__global__ __launch_bounds__(256) void attn_mma()
{
    extern __shared__ __align__(16) char smem[];
    const int tid = threadIdx.x, lane = tid & 31, wid = tid >> 5;
    const int g = lane >> 2, tg = lane & 3;
    const int q0 = blockIdx.x * 128;
    const int bh = blockIdx.y;
    const int b  = bh >> 3, h = bh & 7;

    auto stage = [&](int s, int k0) {
        #pragma unroll
        for (int i = 0; i < 2; i++) {
            int idx = i * 256 + tid, row = idx >> 3, ch = idx & 7;
            size_t src = ((size_t)bh * NL + k0 + row) * NHW + ch * 4;
            int dst = row * 144 + ch * 16;
            cp16(smem + KH_OFF + s * 9216 + dst, g_K   + src);
            cp16(smem + KL_OFF + s * 9216 + dst, g_Klo + src);
            cp16(smem + VH_OFF + s * 9216 + dst, g_V   + src);
            cp16(smem + VL_OFF + s * 9216 + dst, g_Vlo + src);
        }
        #pragma unroll
        for (int i = 0; i < 8; i++) {           // bias 128q x 64k fp32
            int idx = i * 256 + tid, row = idx >> 4, ch = idx & 15;
            cp16(smem + B_OFF + s * 34816 + row * 272 + ch * 16,
                 g_Btf + ((size_t)bh * NL + q0 + row) * NL + k0 + ch * 4);
        }
    };

    // stage Q (once) + tile 0
    #pragma unroll
    for (int i = 0; i < 4; i++) {
        int idx = i * 256 + tid, row = idx >> 3, ch = idx & 7;
        cp16(smem + Q_OFF + row * 144 + ch * 16,
             g_Q + ((size_t)bh * NL + q0 + row) * NHW + ch * 4);
    }
    stage(0, 0);
    cp_commit();
    cp_wait0();
    __syncthreads();

    // preload split Q fragments (A: m16k8 tf32) for this warp's 16 q-rows
    uint32_t aqh[4][4], aql[4][4];
    {
        const float* qb = (const float*)(smem + Q_OFF) + (wid * 16 + g) * 36;
        #pragma unroll
        for (int kk = 0; kk < 4; kk++) {
            float q00 = qb[kk * 8 + tg];
            float q01 = qb[8 * 36 + kk * 8 + tg];
            float q10 = qb[kk * 8 + tg + 4];
            float q11 = qb[8 * 36 + kk * 8 + tg + 4];
            float h00 = tf32_rna_f(q00), h01 = tf32_rna_f(q01);
            float h10 = tf32_rna_f(q10), h11 = tf32_rna_f(q11);
            aqh[kk][0] = __float_as_uint(h00);
            aqh[kk][1] = __float_as_uint(h01);
            aqh[kk][2] = __float_as_uint(h10);
            aqh[kk][3] = __float_as_uint(h11);
            aql[kk][0] = tf32_rna_u(q00 - h00);
            aql[kk][1] = tf32_rna_u(q01 - h01);
            aql[kk][2] = tf32_rna_u(q10 - h10);
            aql[kk][3] = tf32_rna_u(q11 - h11);
        }
    }

    float co[4][4];
    #pragma unroll
    for (int n = 0; n < 4; n++)
        #pragma unroll
        for (int j = 0; j < 4; j++) co[n][j] = 0.f;
    float lsum0 = 0.f, lsum1 = 0.f;

    float* Ps = (float*)(smem + P_OFF) + wid * 16 * 68;

    for (int t = 0; t < 32; t++) {
        const int s = t & 1;
        if (t < 31) stage(s ^ 1, (t + 1) * 64);
        cp_commit();
        cp_wait1();
        __syncthreads();

        const float* KsH = (const float*)(smem + KH_OFF + s * 9216);
        const float* KsL = (const float*)(smem + KL_OFF + s * 9216);
        const float* VsH = (const float*)(smem + VH_OFF + s * 9216);
        const float* VsL = (const float*)(smem + VL_OFF + s * 9216);
        const float* Bs  = (const float*)(smem + B_OFF  + s * 34816);

        // ---- S = Q @ K^T, split-precision 3-MMA
        float c[8][4];
        #pragma unroll
        for (int n = 0; n < 8; n++)
            #pragma unroll
            for (int j = 0; j < 4; j++) c[n][j] = 0.f;
        #pragma unroll
        for (int kk = 0; kk < 4; kk++) {
            #pragma unroll
            for (int n = 0; n < 8; n++) {
                int off = (n * 8 + g) * 36 + kk * 8 + tg;
                uint32_t bh0 = __float_as_uint(KsH[off]);
                uint32_t bh1 = __float_as_uint(KsH[off + 4]);
                uint32_t bl0 = __float_as_uint(KsL[off]);
                uint32_t bl1 = __float_as_uint(KsL[off + 4]);
                mma_tf32(c[n], aqh[kk], bh0, bh1);
                mma_tf32(c[n], aql[kk], bh0, bh1);
                mma_tf32(c[n], aqh[kk], bl0, bl1);
            }
        }

        // ---- softmax (no max subtraction; scores bounded), P rounded rna
        const float* brow = Bs + (wid * 16 + g) * 68;
        #pragma unroll
        for (int n = 0; n < 8; n++) {
            float2 f0 = *(const float2*)(brow + n * 8 + 2 * tg);
            float2 f1 = *(const float2*)(brow + 8 * 68 + n * 8 + 2 * tg);
            uint32_t r0 = tf32_rna_u(__expf(c[n][0] + f0.x));
            uint32_t r1 = tf32_rna_u(__expf(c[n][1] + f0.y));
            uint32_t r2 = tf32_rna_u(__expf(c[n][2] + f1.x));
            uint32_t r3 = tf32_rna_u(__expf(c[n][3] + f1.y));
            float p0 = __uint_as_float(r0), p1 = __uint_as_float(r1);
            float p2 = __uint_as_float(r2), p3 = __uint_as_float(r3);
            lsum0 += p0 + p1; lsum1 += p2 + p3;
            *(float2*)(Ps + g * 68 + n * 8 + 2 * tg)       = make_float2(p0, p1);
            *(float2*)(Ps + (g + 8) * 68 + n * 8 + 2 * tg) = make_float2(p2, p3);
        }
        __syncwarp();

        // ---- O += P @ (V_hi + V_lo), 2-MMA
        #pragma unroll
        for (int kk = 0; kk < 8; kk++) {
            uint32_t pa[4];
            const float* pr = Ps + g * 68 + kk * 8 + tg;
            pa[0] = __float_as_uint(pr[0]);
            pa[1] = __float_as_uint(pr[8 * 68]);
            pa[2] = __float_as_uint(pr[4]);
            pa[3] = __float_as_uint(pr[8 * 68 + 4]);
            #pragma unroll
            for (int n = 0; n < 4; n++) {
                int off = (kk * 8 + tg) * 36 + n * 8 + g;
                uint32_t bh0 = __float_as_uint(VsH[off]);
                uint32_t bh1 = __float_as_uint(VsH[off + 4 * 36]);
                uint32_t bl0 = __float_as_uint(VsL[off]);
                uint32_t bl1 = __float_as_uint(VsL[off + 4 * 36]);
                mma_tf32(co[n], pa, bh0, bh1);
                mma_tf32(co[n], pa, bl0, bl1);
            }
        }
        __syncthreads();
    }

    // ---- epilogue: row sums live on 4 lanes (same g, tg=0..3) -> 2 shuffles
    #pragma unroll
    for (int off = 1; off <= 2; off <<= 1) {
        lsum0 += __shfl_xor_sync(0xffffffffu, lsum0, off);
        lsum1 += __shfl_xor_sync(0xffffffffu, lsum1, off);
    }
    float inv0 = 1.0f / lsum0, inv1 = 1.0f / lsum1;
    int q = q0 + wid * 16 + g;
    float* y0 = g_Y + ((size_t)(b * NL + q)) * NE + h * NHW;
    #pragma unroll
    for (int n = 0; n < 4; n++) {
        *(float2*)(y0 + n * 8 + 2 * tg) =
            make_float2(co[n][0] * inv0, co[n][1] * inv0);
        *(float2*)(y0 + 8 * NE + n * 8 + 2 * tg) =
            make_float2(co[n][2] * inv1, co[n][3] * inv1);
    }
}

// ---------------------------------------------------------------------------
extern "C" void kernel_launch(void* const* d_in, const int* in_sizes, int n_in,
                              void* d_out, int out_size)
{
    const float* x    = (const float*)d_in[0];
    const float* bias = (const float*)d_in[1];
    const float* Wp   = (const float*)d_in[2];
    const float* Wo   = (const float*)d_in[3];
    const float* bo   = (const float*)d_in[4];
    float* out = (float*)d_out;

    float* yptr;
    cudaGetSymbolAddress((void**)&yptr, g_Y);

    cudaFuncSetAttribute(attn_mma, cudaFuncAttributeMaxDynamicSharedMemorySize,
                         SM_TOT);

    gemm_nt<0><<<dim3(32, 12), 256>>>(x, Wp, nullptr, nullptr);
    bias_t<<<(NB * NL * (NL / 2)) / 256, 256>>>(bias);
    attn_mma<<<dim3(NL / 128, NB * NH), 256, SM_TOT>>>();
    gemm_nt<1><<<dim3(32, 4), 256>>>(yptr, Wo, bo, out);
}

// round 13
// speedup vs baseline: 2.0481x; 1.2598x over previous
#include <cuda_runtime.h>
#include <cuda_fp16.h>
#include <cstdint>

#define NL  2048
#define NE  256
#define NH  8
#define NHW 32
#define NB  2

// Scratch (static device globals -- no runtime allocation)
__device__ float   g_Q  [NB*NH*NL*NHW];   // [bh][l][d] fp32 (pre-scaled)
__device__ float   g_K  [NB*NH*NL*NHW];   // tf32-hi
__device__ float   g_Klo[NB*NH*NL*NHW];   // tf32-lo
__device__ float   g_V  [NB*NH*NL*NHW];   // tf32-hi
__device__ float   g_Vlo[NB*NH*NL*NHW];   // tf32-lo
__device__ float   g_Y  [NB*NL*NE];
__device__ __half2 g_Bt [(size_t)NB*NH*NL*NL/2];  // bias^T [b][h][q][k] fp16

typedef unsigned long long u64;

static __device__ __forceinline__ u64 pack2(float lo, float hi) {
    u64 r; asm("mov.b64 %0, {%1,%2};" : "=l"(r) : "f"(lo), "f"(hi)); return r;
}
static __device__ __forceinline__ void unpack2(u64 a, float& lo, float& hi) {
    asm("mov.b64 {%0,%1}, %2;" : "=f"(lo), "=f"(hi) : "l"(a));
}
static __device__ __forceinline__ void fma2(u64& acc, u64 a, u64 b) {
    asm("fma.rn.f32x2 %0, %1, %2, %3;" : "=l"(acc) : "l"(a), "l"(b), "l"(acc));
}
static __device__ __forceinline__ void cp16(void* dst, const void* src) {
    unsigned d = (unsigned)__cvta_generic_to_shared(dst);
    asm volatile("cp.async.cg.shared.global [%0], [%1], 16;" :: "r"(d), "l"(src));
}
static __device__ __forceinline__ void cp_commit() {
    asm volatile("cp.async.commit_group;");
}
static __device__ __forceinline__ void cp_wait1() {
    asm volatile("cp.async.wait_group 1;");
}
static __device__ __forceinline__ void cp_wait0() {
    asm volatile("cp.async.wait_group 0;");
}
static __device__ __forceinline__ uint32_t tf32_rna_u(float x) {
    uint32_t r; asm("cvt.rna.tf32.f32 %0, %1;" : "=r"(r) : "f"(x)); return r;
}
static __device__ __forceinline__ float tf32_rna_f(float x) {
    return __uint_as_float(tf32_rna_u(x));
}
// tf32 mma m16n8k8, fp32 accumulate (arch-portable tensor path)
static __device__ __forceinline__ void mma_tf32(float* c, const uint32_t* a,
                                                uint32_t b0, uint32_t b1) {
    asm volatile(
        "mma.sync.aligned.m16n8k8.row.col.f32.tf32.tf32.f32 "
        "{%0,%1,%2,%3}, {%4,%5,%6,%7}, {%8,%9}, {%0,%1,%2,%3};"
        : "+f"(c[0]), "+f"(c[1]), "+f"(c[2]), "+f"(c[3])
        : "r"(a[0]), "r"(a[1]), "r"(a[2]), "r"(a[3]), "r"(b0), "r"(b1));
}

// ---------------------------------------------------------------------------
// GEMM (NT): C[m][n] = sum_k A[m][k]*W[n][k], K=256. 128x64 tile, 256 thr.
// EPI 0: scatter Q fp32 (scaled), K/V split into tf32 hi/lo.  EPI 1: +bias.
// ---------------------------------------------------------------------------
template<int EPI>
__global__ __launch_bounds__(256) void gemm_nt(const float* __restrict__ A,
                                               const float* __restrict__ W,
                                               const float* __restrict__ bo,
                                               float* __restrict__ out)
{
    __shared__ __align__(16) float As[32][132];
    __shared__ __align__(16) float Bs[32][68];
    const int tid = threadIdx.x;
    const int tx = tid & 15, ty = tid >> 4;
    const int m0 = blockIdx.x * 128, n0 = blockIdx.y * 64;

    u64 acc[4][4];
    #pragma unroll
    for (int p = 0; p < 4; p++)
        #pragma unroll
        for (int j = 0; j < 4; j++) acc[p][j] = 0ULL;

    for (int kc = 0; kc < 256; kc += 32) {
        #pragma unroll
        for (int r = 0; r < 4; r++) {
            int idx = tid + r * 256;
            int row = idx >> 3, c4 = (idx & 7) << 2;
            float4 xa = *(const float4*)&A[(size_t)(m0 + row) * 256 + kc + c4];
            As[c4+0][row] = xa.x; As[c4+1][row] = xa.y;
            As[c4+2][row] = xa.z; As[c4+3][row] = xa.w;
        }
        #pragma unroll
        for (int r = 0; r < 2; r++) {
            int idx = tid + r * 256;
            int row = idx >> 3, c4 = (idx & 7) << 2;
            float4 wa = *(const float4*)&W[(size_t)(n0 + row) * 256 + kc + c4];
            Bs[c4+0][row] = wa.x; Bs[c4+1][row] = wa.y;
            Bs[c4+2][row] = wa.z; Bs[c4+3][row] = wa.w;
        }
        __syncthreads();
        #pragma unroll
        for (int k = 0; k < 32; k++) {
            ulonglong2 aA = *(const ulonglong2*)&As[k][ty * 8];
            ulonglong2 aB = *(const ulonglong2*)&As[k][ty * 8 + 4];
            float4 b4 = *(const float4*)&Bs[k][tx * 4];
            u64 bb;
            bb = pack2(b4.x, b4.x);
            fma2(acc[0][0], aA.x, bb); fma2(acc[1][0], aA.y, bb);
            fma2(acc[2][0], aB.x, bb); fma2(acc[3][0], aB.y, bb);
            bb = pack2(b4.y, b4.y);
            fma2(acc[0][1], aA.x, bb); fma2(acc[1][1], aA.y, bb);
            fma2(acc[2][1], aB.x, bb); fma2(acc[3][1], aB.y, bb);
            bb = pack2(b4.z, b4.z);
            fma2(acc[0][2], aA.x, bb); fma2(acc[1][2], aA.y, bb);
            fma2(acc[2][2], aB.x, bb); fma2(acc[3][2], aB.y, bb);
            bb = pack2(b4.w, b4.w);
            fma2(acc[0][3], aA.x, bb); fma2(acc[1][3], aA.y, bb);
            fma2(acc[2][3], aB.x, bb); fma2(acc[3][3], aB.y, bb);
        }
        __syncthreads();
    }

    #pragma unroll
    for (int p = 0; p < 4; p++) {
        int m = m0 + ty * 8 + 2 * p;
        #pragma unroll
        for (int j = 0; j < 4; j++) {
            float v0, v1; unpack2(acc[p][j], v0, v1);
            int n = n0 + tx * 4 + j;
            if (EPI == 0) {
                int hh = n / 96, rem = n % 96;
                int part = rem >> 5, c = rem & 31;
                int bb_ = m >> 11, l = m & 2047;
                int bh = bb_ * NH + hh;
                size_t base = ((size_t)bh * NL + l) * NHW + c;
                if (part == 0) {
                    g_Q[base]       = v0 * 0.17677669529663687f;
                    g_Q[base + NHW] = v1 * 0.17677669529663687f;
                } else {
                    float* dh = (part == 1) ? g_K   : g_V;
                    float* dl = (part == 1) ? g_Klo : g_Vlo;
                    float h0 = tf32_rna_f(v0), h1 = tf32_rna_f(v1);
                    dh[base]       = h0;
                    dh[base + NHW] = h1;
                    dl[base]       = tf32_rna_f(v0 - h0);
                    dl[base + NHW] = tf32_rna_f(v1 - h1);
                }
            } else {
                float bias_ = bo[n];
                out[(size_t)m * NE + n]       = v0 + bias_;
                out[(size_t)(m + 1) * NE + n] = v1 + bias_;
            }
        }
    }
}

// ---------------------------------------------------------------------------
// bias transpose: [b][q][k][h] fp32 -> [b][h][q][k] fp16 (HBM-bound)
// ---------------------------------------------------------------------------
__global__ __launch_bounds__(256) void bias_t(const float* __restrict__ bias)
{
    size_t idx = (size_t)blockIdx.x * 256 + threadIdx.x;   // over NB*NL*(NL/2)
    int k2 = idx & 1023;
    size_t rest = idx >> 10;
    int q = rest & 2047;
    int b = (int)(rest >> 11);
    const float4* src = (const float4*)(bias + (((size_t)(b * NL + q)) * NL + 2 * k2) * NH);
    float4 a0 = src[0], a1 = src[1], a2 = src[2], a3 = src[3];
    float f[16];
    *(float4*)&f[0]  = a0; *(float4*)&f[4]  = a1;
    *(float4*)&f[8]  = a2; *(float4*)&f[12] = a3;
    #pragma unroll
    for (int h = 0; h < NH; h++)
        g_Bt[((size_t)(b * NH + h) * NL + q) * (NL / 2) + k2] =
            __floats2half2_rn(f[h], f[8 + h]);
}

// ---------------------------------------------------------------------------
// Split-precision tf32 mma.sync attention, k-tile 32, 2 CTAs/SM (one wave).
// CTA = (b,h,128q), 8 warps x 16q. S = 3-MMA split QK; P rna-rounded;
// O += P(V_hi+V_lo). Bias fp16 (80B row pitch -- 16B-aligned for cp.async).
// ---------------------------------------------------------------------------
#define QS_OFF  0          // 128 x 144B                    = 18432
#define KH_OFF  18432      // 2 stages x 32 x 144B (4608)   = 9216
#define KL_OFF  27648
#define VH_OFF  36864
#define VL_OFF  46080
#define B_OFF   55296      // 2 stages x 128 x 80B (10240)  = 20480
#define P_OFF   75776      // 8 warps x 16 x 36 floats      = 18432
#define SM_TOT  94208
#define B_PITCH 40         // halves per bias row (80 bytes)

__global__ __launch_bounds__(256, 2) void attn_mma()
{
    extern __shared__ __align__(16) char smem[];
    const int tid = threadIdx.x, lane = tid & 31, wid = tid >> 5;
    const int g = lane >> 2, tg = lane & 3;
    const int q0 = blockIdx.x * 128;
    const int bh = blockIdx.y;
    const int b  = bh >> 3, h = bh & 7;

    const __half* btp = (const __half*)g_Bt;

    const int krow = tid >> 3, kch = tid & 7;
    auto stage = [&](int s, int k0) {
        size_t src = ((size_t)bh * NL + k0 + krow) * NHW + kch * 4;
        int dst = s * 4608 + krow * 144 + kch * 16;
        cp16(smem + KH_OFF + dst, g_K   + src);
        cp16(smem + KL_OFF + dst, g_Klo + src);
        cp16(smem + VH_OFF + dst, g_V   + src);
        cp16(smem + VL_OFF + dst, g_Vlo + src);
        #pragma unroll
        for (int i = 0; i < 2; i++) {
            int idx = i * 256 + tid, row = idx >> 2, ch = idx & 3;
            cp16(smem + B_OFF + s * 10240 + row * 80 + ch * 16,
                 btp + ((size_t)bh * NL + q0 + row) * NL + k0 + ch * 8);
        }
    };

    // stage Q (once) + tile 0
    #pragma unroll
    for (int i = 0; i < 4; i++) {
        int idx = i * 256 + tid, row = idx >> 3, ch = idx & 7;
        cp16(smem + QS_OFF + row * 144 + ch * 16,
             g_Q + ((size_t)bh * NL + q0 + row) * NHW + ch * 4);
    }
    stage(0, 0);
    cp_commit();
    cp_wait0();
    __syncthreads();

    // preload split Q fragments (A: m16k8 tf32) for this warp's 16 q-rows
    uint32_t aqh[4][4], aql[4][4];
    {
        const float* qb = (const float*)(smem + QS_OFF) + (wid * 16 + g) * 36;
        #pragma unroll
        for (int kk = 0; kk < 4; kk++) {
            float q00 = qb[kk * 8 + tg];
            float q01 = qb[8 * 36 + kk * 8 + tg];
            float q10 = qb[kk * 8 + tg + 4];
            float q11 = qb[8 * 36 + kk * 8 + tg + 4];
            float h00 = tf32_rna_f(q00), h01 = tf32_rna_f(q01);
            float h10 = tf32_rna_f(q10), h11 = tf32_rna_f(q11);
            aqh[kk][0] = __float_as_uint(h00);
            aqh[kk][1] = __float_as_uint(h01);
            aqh[kk][2] = __float_as_uint(h10);
            aqh[kk][3] = __float_as_uint(h11);
            aql[kk][0] = tf32_rna_u(q00 - h00);
            aql[kk][1] = tf32_rna_u(q01 - h01);
            aql[kk][2] = tf32_rna_u(q10 - h10);
            aql[kk][3] = tf32_rna_u(q11 - h11);
        }
    }

    float co[4][4];
    #pragma unroll
    for (int n = 0; n < 4; n++)
        #pragma unroll
        for (int j = 0; j < 4; j++) co[n][j] = 0.f;
    float lsum0 = 0.f, lsum1 = 0.f;

    float* Ps = (float*)(smem + P_OFF) + wid * 16 * 36;

    for (int t = 0; t < 64; t++) {
        const int s = t & 1;
        if (t < 63) stage(s ^ 1, (t + 1) * 32);
        cp_commit();
        cp_wait1();
        __syncthreads();

        const float* KsH = (const float*)(smem + KH_OFF + s * 4608);
        const float* KsL = (const float*)(smem + KL_OFF + s * 4608);
        const float* VsH = (const float*)(smem + VH_OFF + s * 4608);
        const float* VsL = (const float*)(smem + VL_OFF + s * 4608);

        // ---- S = Q @ K^T, split-precision 3-MMA (4 n-blocks of 8 keys)
        float c[4][4];
        #pragma unroll
        for (int n = 0; n < 4; n++)
            #pragma unroll
            for (int j = 0; j < 4; j++) c[n][j] = 0.f;
        #pragma unroll
        for (int kk = 0; kk < 4; kk++) {
            #pragma unroll
            for (int n = 0; n < 4; n++) {
                int off = (n * 8 + g) * 36 + kk * 8 + tg;
                uint32_t bh0 = __float_as_uint(KsH[off]);
                uint32_t bh1 = __float_as_uint(KsH[off + 4]);
                uint32_t bl0 = __float_as_uint(KsL[off]);
                uint32_t bl1 = __float_as_uint(KsL[off + 4]);
                mma_tf32(c[n], aqh[kk], bh0, bh1);
                mma_tf32(c[n], aql[kk], bh0, bh1);
                mma_tf32(c[n], aqh[kk], bl0, bl1);
            }
        }

        // ---- softmax (no max subtraction; scores bounded), P rounded rna
        const __half* brow = (const __half*)(smem + B_OFF + s * 10240)
                           + (wid * 16 + g) * B_PITCH;
        #pragma unroll
        for (int n = 0; n < 4; n++) {
            float2 f0 = __half22float2(*(const __half2*)(brow + n * 8 + 2 * tg));
            float2 f1 = __half22float2(*(const __half2*)(brow + 8 * B_PITCH + n * 8 + 2 * tg));
            float p0 = __uint_as_float(tf32_rna_u(__expf(c[n][0] + f0.x)));
            float p1 = __uint_as_float(tf32_rna_u(__expf(c[n][1] + f0.y)));
            float p2 = __uint_as_float(tf32_rna_u(__expf(c[n][2] + f1.x)));
            float p3 = __uint_as_float(tf32_rna_u(__expf(c[n][3] + f1.y)));
            lsum0 += p0 + p1; lsum1 += p2 + p3;
            *(float2*)(Ps + g * 36 + n * 8 + 2 * tg)       = make_float2(p0, p1);
            *(float2*)(Ps + (g + 8) * 36 + n * 8 + 2 * tg) = make_float2(p2, p3);
        }
        __syncwarp();

        // ---- O += P @ (V_hi + V_lo), 2-MMA (4 n-blocks of 8 dims)
        #pragma unroll
        for (int kk = 0; kk < 4; kk++) {
            uint32_t pa[4];
            const float* pr = Ps + g * 36 + kk * 8 + tg;
            pa[0] = __float_as_uint(pr[0]);
            pa[1] = __float_as_uint(pr[8 * 36]);
            pa[2] = __float_as_uint(pr[4]);
            pa[3] = __float_as_uint(pr[8 * 36 + 4]);
            #pragma unroll
            for (int n = 0; n < 4; n++) {
                int off = (kk * 8 + tg) * 36 + n * 8 + g;
                uint32_t bh0 = __float_as_uint(VsH[off]);
                uint32_t bh1 = __float_as_uint(VsH[off + 4 * 36]);
                uint32_t bl0 = __float_as_uint(VsL[off]);
                uint32_t bl1 = __float_as_uint(VsL[off + 4 * 36]);
                mma_tf32(co[n], pa, bh0, bh1);
                mma_tf32(co[n], pa, bl0, bl1);
            }
        }
        __syncthreads();
    }

    // ---- epilogue: row sums live on 4 lanes (same g, tg=0..3) -> 2 shuffles
    #pragma unroll
    for (int off = 1; off <= 2; off <<= 1) {
        lsum0 += __shfl_xor_sync(0xffffffffu, lsum0, off);
        lsum1 += __shfl_xor_sync(0xffffffffu, lsum1, off);
    }
    float inv0 = 1.0f / lsum0, inv1 = 1.0f / lsum1;
    int q = q0 + wid * 16 + g;
    float* y0 = g_Y + ((size_t)(b * NL + q)) * NE + h * NHW;
    #pragma unroll
    for (int n = 0; n < 4; n++) {
        *(float2*)(y0 + n * 8 + 2 * tg) =
            make_float2(co[n][0] * inv0, co[n][1] * inv0);
        *(float2*)(y0 + 8 * NE + n * 8 + 2 * tg) =
            make_float2(co[n][2] * inv1, co[n][3] * inv1);
    }
}

// ---------------------------------------------------------------------------
extern "C" void kernel_launch(void* const* d_in, const int* in_sizes, int n_in,
                              void* d_out, int out_size)
{
    const float* x    = (const float*)d_in[0];
    const float* bias = (const float*)d_in[1];
    const float* Wp   = (const float*)d_in[2];
    const float* Wo   = (const float*)d_in[3];
    const float* bo   = (const float*)d_in[4];
    float* out = (float*)d_out;

    float* yptr;
    cudaGetSymbolAddress((void**)&yptr, g_Y);

    cudaFuncSetAttribute(attn_mma, cudaFuncAttributeMaxDynamicSharedMemorySize,
                         SM_TOT);

    gemm_nt<0><<<dim3(32, 12), 256>>>(x, Wp, nullptr, nullptr);
    bias_t<<<(NB * NL * (NL / 2)) / 256, 256>>>(bias);
    attn_mma<<<dim3(NL / 128, NB * NH), 256, SM_TOT>>>();
    gemm_nt<1><<<dim3(32, 4), 256>>>(yptr, Wo, bo, out);
}

// round 14
// speedup vs baseline: 2.2832x; 1.1148x over previous
#include <cuda_runtime.h>
#include <cuda_fp16.h>
#include <cstdint>

#define NL  2048
#define NE  256
#define NH  8
#define NHW 32
#define NB  2

// Scratch (static device globals -- no runtime allocation)
__device__ float   g_Q   [NB*NH*NL*NHW];   // [bh][l][d] fp32 (pre-scaled)
__device__ float   g_K   [NB*NH*NL*NHW];   // [bh][l][d] tf32-hi
__device__ float   g_Klo [NB*NH*NL*NHW];   // [bh][l][d] tf32-lo
__device__ float   g_Vt  [NB*NH*NHW*NL];   // [bh][d][l] tf32-hi (transposed)
__device__ float   g_Vtlo[NB*NH*NHW*NL];   // [bh][d][l] tf32-lo
__device__ float   g_Y   [NB*NL*NE];
__device__ __half2 g_Bt  [(size_t)NB*NH*NL*NL/2]; // bias^T [b][h][q][k] fp16

typedef unsigned long long u64;

static __device__ __forceinline__ u64 pack2(float lo, float hi) {
    u64 r; asm("mov.b64 %0, {%1,%2};" : "=l"(r) : "f"(lo), "f"(hi)); return r;
}
static __device__ __forceinline__ void unpack2(u64 a, float& lo, float& hi) {
    asm("mov.b64 {%0,%1}, %2;" : "=f"(lo), "=f"(hi) : "l"(a));
}
static __device__ __forceinline__ void fma2(u64& acc, u64 a, u64 b) {
    asm("fma.rn.f32x2 %0, %1, %2, %3;" : "=l"(acc) : "l"(a), "l"(b), "l"(acc));
}
static __device__ __forceinline__ void cp16(void* dst, const void* src) {
    unsigned d = (unsigned)__cvta_generic_to_shared(dst);
    asm volatile("cp.async.cg.shared.global [%0], [%1], 16;" :: "r"(d), "l"(src));
}
static __device__ __forceinline__ void cp_commit() {
    asm volatile("cp.async.commit_group;");
}
static __device__ __forceinline__ void cp_wait1() {
    asm volatile("cp.async.wait_group 1;");
}
static __device__ __forceinline__ void cp_wait0() {
    asm volatile("cp.async.wait_group 0;");
}
static __device__ __forceinline__ uint32_t smem_u32(const void* p) {
    return (uint32_t)__cvta_generic_to_shared(p);
}
static __device__ __forceinline__ uint32_t tf32_rna_u(float x) {
    uint32_t r; asm("cvt.rna.tf32.f32 %0, %1;" : "=r"(r) : "f"(x)); return r;
}
static __device__ __forceinline__ float tf32_rna_f(float x) {
    return __uint_as_float(tf32_rna_u(x));
}
// tf32 mma m16n8k8, fp32 accumulate (arch-portable tensor path)
static __device__ __forceinline__ void mma_tf32(float* c, const uint32_t* a,
                                                uint32_t b0, uint32_t b1) {
    asm volatile(
        "mma.sync.aligned.m16n8k8.row.col.f32.tf32.tf32.f32 "
        "{%0,%1,%2,%3}, {%4,%5,%6,%7}, {%8,%9}, {%0,%1,%2,%3};"
        : "+f"(c[0]), "+f"(c[1]), "+f"(c[2]), "+f"(c[3])
        : "r"(a[0]), "r"(a[1]), "r"(a[2]), "r"(a[3]), "r"(b0), "r"(b1));
}
// ldmatrix x4 (b16 view of b32 tiles)
static __device__ __forceinline__ void ldsm4(uint32_t* r, uint32_t addr) {
    asm volatile("ldmatrix.sync.aligned.m8n8.x4.shared.b16 {%0,%1,%2,%3}, [%4];"
        : "=r"(r[0]), "=r"(r[1]), "=r"(r[2]), "=r"(r[3]) : "r"(addr));
}

// ---------------------------------------------------------------------------
// GEMM (NT): C[m][n] = sum_k A[m][k]*W[n][k], K=256. 128x64 tile, 256 thr.
// EPI 0: Q fp32 (scaled); K hi/lo [bh][l][d]; V hi/lo transposed [bh][d][l].
// EPI 1: out + bias.
// ---------------------------------------------------------------------------
template<int EPI>
__global__ __launch_bounds__(256) void gemm_nt(const float* __restrict__ A,
                                               const float* __restrict__ W,
                                               const float* __restrict__ bo,
                                               float* __restrict__ out)
{
    __shared__ __align__(16) float As[32][132];
    __shared__ __align__(16) float Bs[32][68];
    const int tid = threadIdx.x;
    const int tx = tid & 15, ty = tid >> 4;
    const int m0 = blockIdx.x * 128, n0 = blockIdx.y * 64;

    u64 acc[4][4];
    #pragma unroll
    for (int p = 0; p < 4; p++)
        #pragma unroll
        for (int j = 0; j < 4; j++) acc[p][j] = 0ULL;

    for (int kc = 0; kc < 256; kc += 32) {
        #pragma unroll
        for (int r = 0; r < 4; r++) {
            int idx = tid + r * 256;
            int row = idx >> 3, c4 = (idx & 7) << 2;
            float4 xa = *(const float4*)&A[(size_t)(m0 + row) * 256 + kc + c4];
            As[c4+0][row] = xa.x; As[c4+1][row] = xa.y;
            As[c4+2][row] = xa.z; As[c4+3][row] = xa.w;
        }
        #pragma unroll
        for (int r = 0; r < 2; r++) {
            int idx = tid + r * 256;
            int row = idx >> 3, c4 = (idx & 7) << 2;
            float4 wa = *(const float4*)&W[(size_t)(n0 + row) * 256 + kc + c4];
            Bs[c4+0][row] = wa.x; Bs[c4+1][row] = wa.y;
            Bs[c4+2][row] = wa.z; Bs[c4+3][row] = wa.w;
        }
        __syncthreads();
        #pragma unroll
        for (int k = 0; k < 32; k++) {
            ulonglong2 aA = *(const ulonglong2*)&As[k][ty * 8];
            ulonglong2 aB = *(const ulonglong2*)&As[k][ty * 8 + 4];
            float4 b4 = *(const float4*)&Bs[k][tx * 4];
            u64 bb;
            bb = pack2(b4.x, b4.x);
            fma2(acc[0][0], aA.x, bb); fma2(acc[1][0], aA.y, bb);
            fma2(acc[2][0], aB.x, bb); fma2(acc[3][0], aB.y, bb);
            bb = pack2(b4.y, b4.y);
            fma2(acc[0][1], aA.x, bb); fma2(acc[1][1], aA.y, bb);
            fma2(acc[2][1], aB.x, bb); fma2(acc[3][1], aB.y, bb);
            bb = pack2(b4.z, b4.z);
            fma2(acc[0][2], aA.x, bb); fma2(acc[1][2], aA.y, bb);
            fma2(acc[2][2], aB.x, bb); fma2(acc[3][2], aB.y, bb);
            bb = pack2(b4.w, b4.w);
            fma2(acc[0][3], aA.x, bb); fma2(acc[1][3], aA.y, bb);
            fma2(acc[2][3], aB.x, bb); fma2(acc[3][3], aB.y, bb);
        }
        __syncthreads();
    }

    #pragma unroll
    for (int p = 0; p < 4; p++) {
        int m = m0 + ty * 8 + 2 * p;
        #pragma unroll
        for (int j = 0; j < 4; j++) {
            float v0, v1; unpack2(acc[p][j], v0, v1);
            int n = n0 + tx * 4 + j;
            if (EPI == 0) {
                int hh = n / 96, rem = n % 96;
                int part = rem >> 5, c = rem & 31;
                int bb_ = m >> 11, l = m & 2047;
                int bh = bb_ * NH + hh;
                if (part == 0) {
                    size_t base = ((size_t)bh * NL + l) * NHW + c;
                    g_Q[base]       = v0 * 0.17677669529663687f;
                    g_Q[base + NHW] = v1 * 0.17677669529663687f;
                } else {
                    float h0 = tf32_rna_f(v0), h1 = tf32_rna_f(v1);
                    float l0 = tf32_rna_f(v0 - h0), l1 = tf32_rna_f(v1 - h1);
                    if (part == 1) {
                        size_t base = ((size_t)bh * NL + l) * NHW + c;
                        g_K  [base] = h0; g_K  [base + NHW] = h1;
                        g_Klo[base] = l0; g_Klo[base + NHW] = l1;
                    } else {
                        size_t base = ((size_t)bh * NHW + c) * NL + l;
                        g_Vt  [base] = h0; g_Vt  [base + 1] = h1;
                        g_Vtlo[base] = l0; g_Vtlo[base + 1] = l1;
                    }
                }
            } else {
                float bias_ = bo[n];
                out[(size_t)m * NE + n]       = v0 + bias_;
                out[(size_t)(m + 1) * NE + n] = v1 + bias_;
            }
        }
    }
}

// ---------------------------------------------------------------------------
// bias transpose: [b][q][k][h] fp32 -> [b][h][q][k] fp16 (HBM-bound)
// ---------------------------------------------------------------------------
__global__ __launch_bounds__(256) void bias_t(const float* __restrict__ bias)
{
    size_t idx = (size_t)blockIdx.x * 256 + threadIdx.x;   // over NB*NL*(NL/2)
    int k2 = idx & 1023;
    size_t rest = idx >> 10;
    int q = rest & 2047;
    int b = (int)(rest >> 11);
    const float4* src = (const float4*)(bias + (((size_t)(b * NL + q)) * NL + 2 * k2) * NH);
    float4 a0 = src[0], a1 = src[1], a2 = src[2], a3 = src[3];
    float f[16];
    *(float4*)&f[0]  = a0; *(float4*)&f[4]  = a1;
    *(float4*)&f[8]  = a2; *(float4*)&f[12] = a3;
    #pragma unroll
    for (int h = 0; h < NH; h++)
        g_Bt[((size_t)(b * NH + h) * NL + q) * (NL / 2) + k2] =
            __floats2half2_rn(f[h], f[8 + h]);
}

// ---------------------------------------------------------------------------
// Split-precision tf32 mma.sync attention with ldmatrix fragment loads.
// CTA = (b,h,128q), 8 warps x 16q, k-tile 32, 2 CTAs/SM.
// K smem [k][d] (144B pitch), V smem [d][k] (from g_Vt), P smem [q][k].
// All mma fragments loaded via ldmatrix.x4.b16 (4 tiles of 8x4 b32 each).
// ---------------------------------------------------------------------------
#define QS_OFF  0          // 128 x 144B                    = 18432
#define KH_OFF  18432      // 2 stages x 32 x 144B (4608)
#define KL_OFF  27648
#define VH_OFF  36864      // Vt tiles: 32 d-rows x 144B
#define VL_OFF  46080
#define B_OFF   55296      // 2 stages x 128 x 80B (10240)  = 20480
#define P_OFF   75776      // 8 warps x 16 x 144B           = 18432
#define SM_TOT  94208
#define B_PITCH 40         // halves per bias row (80 bytes)

__global__ __launch_bounds__(256, 2) void attn_mma()
{
    extern __shared__ __align__(16) char smem[];
    const int tid = threadIdx.x, lane = tid & 31, wid = tid >> 5;
    const int g = lane >> 2, tg = lane & 3;
    const int q0 = blockIdx.x * 128;
    const int bh = blockIdx.y;
    const int b  = bh >> 3, h = bh & 7;

    const __half* btp = (const __half*)g_Bt;

    const int krow = tid >> 3, kch = tid & 7;
    auto stage = [&](int s, int k0) {
        // K tile: 32 keys x 32 d, [k][d]
        cp16(smem + KH_OFF + s * 4608 + krow * 144 + kch * 16,
             g_K   + ((size_t)bh * NL + k0 + krow) * NHW + kch * 4);
        cp16(smem + KL_OFF + s * 4608 + krow * 144 + kch * 16,
             g_Klo + ((size_t)bh * NL + k0 + krow) * NHW + kch * 4);
        // V tile: 32 d x 32 keys, [d][k] (gmem already transposed)
        cp16(smem + VH_OFF + s * 4608 + krow * 144 + kch * 16,
             g_Vt   + ((size_t)bh * NHW + krow) * NL + k0 + kch * 4);
        cp16(smem + VL_OFF + s * 4608 + krow * 144 + kch * 16,
             g_Vtlo + ((size_t)bh * NHW + krow) * NL + k0 + kch * 4);
        // bias tile: 128q x 32k fp16, 80B pitch
        #pragma unroll
        for (int i = 0; i < 2; i++) {
            int idx = i * 256 + tid, row = idx >> 2, ch = idx & 3;
            cp16(smem + B_OFF + s * 10240 + row * 80 + ch * 16,
                 btp + ((size_t)bh * NL + q0 + row) * NL + k0 + ch * 8);
        }
    };

    // stage Q (once) + tile 0
    #pragma unroll
    for (int i = 0; i < 4; i++) {
        int idx = i * 256 + tid, row = idx >> 3, ch = idx & 7;
        cp16(smem + QS_OFF + row * 144 + ch * 16,
             g_Q + ((size_t)bh * NL + q0 + row) * NHW + ch * 4);
    }
    stage(0, 0);
    cp_commit();
    cp_wait0();
    __syncthreads();

    // preload split Q fragments (A: m16k8 tf32) for this warp's 16 q-rows
    uint32_t aqh[4][4], aql[4][4];
    {
        const float* qb = (const float*)(smem + QS_OFF) + (wid * 16 + g) * 36;
        #pragma unroll
        for (int kk = 0; kk < 4; kk++) {
            float q00 = qb[kk * 8 + tg];
            float q01 = qb[8 * 36 + kk * 8 + tg];
            float q10 = qb[kk * 8 + tg + 4];
            float q11 = qb[8 * 36 + kk * 8 + tg + 4];
            float h00 = tf32_rna_f(q00), h01 = tf32_rna_f(q01);
            float h10 = tf32_rna_f(q10), h11 = tf32_rna_f(q11);
            aqh[kk][0] = __float_as_uint(h00);
            aqh[kk][1] = __float_as_uint(h01);
            aqh[kk][2] = __float_as_uint(h10);
            aqh[kk][3] = __float_as_uint(h11);
            aql[kk][0] = tf32_rna_u(q00 - h00);
            aql[kk][1] = tf32_rna_u(q01 - h01);
            aql[kk][2] = tf32_rna_u(q10 - h10);
            aql[kk][3] = tf32_rna_u(q11 - h11);
        }
    }

    // ldmatrix per-lane address invariants
    const uint32_t sb = smem_u32(smem);
    const int r7 = lane & 7, h8 = (lane >> 3) & 1, hi16 = lane >> 4;
    const uint32_t inv_b = r7 * 144 + h8 * 16 + hi16 * 1152;   // B-frags (K/V)
    const uint32_t inv_a = r7 * 144 + h8 * 1152 + hi16 * 16;   // A-frags (P)
    const uint32_t aKH = sb + KH_OFF + inv_b;
    const uint32_t aKL = sb + KL_OFF + inv_b;
    const uint32_t aVH = sb + VH_OFF + inv_b;
    const uint32_t aVL = sb + VL_OFF + inv_b;
    const uint32_t aP  = sb + P_OFF + wid * 2304 + inv_a;

    float co[4][4];
    #pragma unroll
    for (int n = 0; n < 4; n++)
        #pragma unroll
        for (int j = 0; j < 4; j++) co[n][j] = 0.f;
    float lsum0 = 0.f, lsum1 = 0.f;

    float* Ps = (float*)(smem + P_OFF) + wid * 16 * 36;

    for (int t = 0; t < 64; t++) {
        const int s = t & 1;
        if (t < 63) stage(s ^ 1, (t + 1) * 32);
        cp_commit();
        cp_wait1();
        __syncthreads();
        const uint32_t so = s * 4608;

        // ---- S = Q @ K^T, split-precision 3-MMA
        float c[4][4];
        #pragma unroll
        for (int n = 0; n < 4; n++)
            #pragma unroll
            for (int j = 0; j < 4; j++) c[n][j] = 0.f;
        #pragma unroll
        for (int kk = 0; kk < 4; kk++) {
            uint32_t bhf[8], blf[8];
            ldsm4(bhf,     aKH + so + kk * 32);
            ldsm4(bhf + 4, aKH + so + kk * 32 + 2304);
            ldsm4(blf,     aKL + so + kk * 32);
            ldsm4(blf + 4, aKL + so + kk * 32 + 2304);
            #pragma unroll
            for (int n = 0; n < 4; n++) {
                mma_tf32(c[n], aqh[kk], bhf[2 * n], bhf[2 * n + 1]);
                mma_tf32(c[n], aql[kk], bhf[2 * n], bhf[2 * n + 1]);
                mma_tf32(c[n], aqh[kk], blf[2 * n], blf[2 * n + 1]);
            }
        }

        // ---- softmax (no max subtraction; scores bounded), P rounded rna
        const __half* brow = (const __half*)(smem + B_OFF + s * 10240)
                           + (wid * 16 + g) * B_PITCH;
        #pragma unroll
        for (int n = 0; n < 4; n++) {
            float2 f0 = __half22float2(*(const __half2*)(brow + n * 8 + 2 * tg));
            float2 f1 = __half22float2(*(const __half2*)(brow + 8 * B_PITCH + n * 8 + 2 * tg));
            float p0 = __uint_as_float(tf32_rna_u(__expf(c[n][0] + f0.x)));
            float p1 = __uint_as_float(tf32_rna_u(__expf(c[n][1] + f0.y)));
            float p2 = __uint_as_float(tf32_rna_u(__expf(c[n][2] + f1.x)));
            float p3 = __uint_as_float(tf32_rna_u(__expf(c[n][3] + f1.y)));
            lsum0 += p0 + p1; lsum1 += p2 + p3;
            *(float2*)(Ps + g * 36 + n * 8 + 2 * tg)       = make_float2(p0, p1);
            *(float2*)(Ps + (g + 8) * 36 + n * 8 + 2 * tg) = make_float2(p2, p3);
        }
        __syncwarp();

        // ---- O += P @ (V_hi + V_lo)
        #pragma unroll
        for (int kk = 0; kk < 4; kk++) {
            uint32_t pa[4], vhf[8], vlf[8];
            ldsm4(pa, aP + kk * 32);
            ldsm4(vhf,     aVH + so + kk * 32);
            ldsm4(vhf + 4, aVH + so + kk * 32 + 2304);
            ldsm4(vlf,     aVL + so + kk * 32);
            ldsm4(vlf + 4, aVL + so + kk * 32 + 2304);
            #pragma unroll
            for (int n = 0; n < 4; n++) {
                mma_tf32(co[n], pa, vhf[2 * n], vhf[2 * n + 1]);
                mma_tf32(co[n], pa, vlf[2 * n], vlf[2 * n + 1]);
            }
        }
        __syncthreads();
    }

    // ---- epilogue: row sums live on 4 lanes (same g, tg=0..3) -> 2 shuffles
    #pragma unroll
    for (int off = 1; off <= 2; off <<= 1) {
        lsum0 += __shfl_xor_sync(0xffffffffu, lsum0, off);
        lsum1 += __shfl_xor_sync(0xffffffffu, lsum1, off);
    }
    float inv0 = 1.0f / lsum0, inv1 = 1.0f / lsum1;
    int q = q0 + wid * 16 + g;
    float* y0 = g_Y + ((size_t)(b * NL + q)) * NE + h * NHW;
    #pragma unroll
    for (int n = 0; n < 4; n++) {
        *(float2*)(y0 + n * 8 + 2 * tg) =
            make_float2(co[n][0] * inv0, co[n][1] * inv0);
        *(float2*)(y0 + 8 * NE + n * 8 + 2 * tg) =
            make_float2(co[n][2] * inv1, co[n][3] * inv1);
    }
}

// ---------------------------------------------------------------------------
extern "C" void kernel_launch(void* const* d_in, const int* in_sizes, int n_in,
                              void* d_out, int out_size)
{
    const float* x    = (const float*)d_in[0];
    const float* bias = (const float*)d_in[1];
    const float* Wp   = (const float*)d_in[2];
    const float* Wo   = (const float*)d_in[3];
    const float* bo   = (const float*)d_in[4];
    float* out = (float*)d_out;

    float* yptr;
    cudaGetSymbolAddress((void**)&yptr, g_Y);

    cudaFuncSetAttribute(attn_mma, cudaFuncAttributeMaxDynamicSharedMemorySize,
                         SM_TOT);

    gemm_nt<0><<<dim3(32, 12), 256>>>(x, Wp, nullptr, nullptr);
    bias_t<<<(NB * NL * (NL / 2)) / 256, 256>>>(bias);
    attn_mma<<<dim3(NL / 128, NB * NH), 256, SM_TOT>>>();
    gemm_nt<1><<<dim3(32, 4), 256>>>(yptr, Wo, bo, out);
}